// round 15
// baseline (speedup 1.0000x reference)
#include <cuda_runtime.h>
#include <cuda_fp16.h>
#include <cuda_bf16.h>

// Problem constants
#define B    8
#define HIN  256
#define WIN  256
#define CV4  16      // C/4 channel chunks per pixel (C=64)
#define HP   64
#define WP   64

// Static device scratch: fp16 column sums (16.7 MB) + fp16 pooled (4 MB)
__device__ uint2 g_colsum[B * HP * WIN * CV4];
__device__ uint2 g_pooled[B * HP * WP  * CV4];

__device__ __forceinline__ void acc4(float4& a, const float4 v) {
    a.x += v.x; a.y += v.y; a.z += v.z; a.w += v.w;
}
__device__ __forceinline__ float4 blend2(float4 p, float wp, float4 q, float wq) {
    float4 r;
    r.x = p.x * wp + q.x * wq;
    r.y = p.y * wp + q.y * wq;
    r.z = p.z * wp + q.z * wq;
    r.w = p.w * wp + q.w * wq;
    return r;
}
__device__ __forceinline__ uint2 pack_h4(float4 v) {
    __half2 lo = __floats2half2_rn(v.x, v.y);
    __half2 hi = __floats2half2_rn(v.z, v.w);
    uint2 u;
    u.x = *reinterpret_cast<unsigned int*>(&lo);
    u.y = *reinterpret_cast<unsigned int*>(&hi);
    return u;
}
__device__ __forceinline__ float4 unpack_h4(uint2 u) {
    __half2 lo = *reinterpret_cast<__half2*>(&u.x);
    __half2 hi = *reinterpret_cast<__half2*>(&u.y);
    float2 a = __half22float2(lo);
    float2 b = __half22float2(hi);
    return make_float4(a.x, a.y, b.x, b.y);
}

// PDL primitives
__device__ __forceinline__ void pdl_wait() {
    asm volatile("griddepcontrol.wait;" ::: "memory");
}
__device__ __forceinline__ void pdl_trigger() {
    asm volatile("griddepcontrol.launch_dependents;" ::: "memory");
}

// ---------------------------------------------------------------------------
// K1: column pool (sum over y-window of 6, stride 4, pad 1/1), fp16 output.
// Streaming, one task per thread — proven 24.7us / 73% DRAM shape (R11).
// ---------------------------------------------------------------------------
__global__ __launch_bounds__(256) void colpool_kernel(const float4* __restrict__ in4) {
    int tid = blockIdx.x * 256 + threadIdx.x;   // B*HP*WIN*CV4 = 2,097,152
    int c4 = tid & 15;
    int x  = (tid >> 4) & 255;
    int oy = (tid >> 12) & 63;
    int b  = tid >> 18;

    int r0 = oy * 4 - 1;
    const float4* p = in4 + (((size_t)b * HIN) * WIN + x) * CV4 + c4;

    float4 s = make_float4(0.f, 0.f, 0.f, 0.f);
    if (oy != 0 && oy != 63) {
        const float4* q = p + (size_t)r0 * WIN * CV4;
        #pragma unroll
        for (int j = 0; j < 6; ++j)
            acc4(s, __ldg(q + (size_t)j * WIN * CV4));
    } else {
        #pragma unroll
        for (int j = 0; j < 6; ++j) {
            int r = r0 + j;
            if ((unsigned)r < 256u)
                acc4(s, __ldg(p + (size_t)r * WIN * CV4));
        }
    }
    g_colsum[tid] = pack_h4(s);
    pdl_trigger();   // all threads done storing -> dependents may launch
}

// ---------------------------------------------------------------------------
// K2: row pool (fp32 accumulate of fp16 colsums) + divide, fp16 out. PDL
// consumer of K1 and producer for K3.
// ---------------------------------------------------------------------------
__global__ __launch_bounds__(256) void rowpool_kernel() {
    int tid = blockIdx.x * 256 + threadIdx.x;   // B*HP*WP*CV4 = 524,288
    int c4 = tid & 15;
    int ox = (tid >> 4) & 63;
    int oy = (tid >> 10) & 63;
    int b  = tid >> 16;

    int x0 = ox * 4 - 1;
    const uint2* p = g_colsum + (((size_t)b * HP + oy) * WIN) * CV4 + c4;

    pdl_wait();      // colsum writes visible from here

    float4 s = make_float4(0.f, 0.f, 0.f, 0.f);
    if (ox != 0 && ox != 63) {
        const uint2* q = p + (size_t)x0 * CV4;
        #pragma unroll
        for (int j = 0; j < 6; ++j)
            acc4(s, unpack_h4(__ldg(q + (size_t)j * CV4)));
    } else {
        #pragma unroll
        for (int j = 0; j < 6; ++j) {
            int x = x0 + j;
            if ((unsigned)x < 256u)
                acc4(s, unpack_h4(__ldg(p + (size_t)x * CV4)));
        }
    }

    int nr = 6 - (oy == 0) - (oy == 63);
    int nc = 6 - (ox == 0) - (ox == 63);
    float inv = 1.0f / (float)(nr * nc);
    g_pooled[tid] = pack_h4(make_float4(s.x * inv, s.y * inv, s.z * inv, s.w * inv));
    pdl_trigger();
}

// ---------------------------------------------------------------------------
// K3: unaverage pool (x4 upsample), direct streaming (proven 22.2-22.6us),
// PDL consumer of K2.
// ---------------------------------------------------------------------------
__device__ __forceinline__ float d2s(float d) {
    if (d < 5.5f)   return (d - 2.0f) * (1.0f / 3.5f);
    if (d > 249.5f) return (d - 249.5f) * (1.0f / 3.5f) + 62.0f;
    return (d - 1.5f) * 0.25f;
}

__global__ __launch_bounds__(256, 6) void up_kernel(float4* __restrict__ out4) {
    int tid = blockIdx.x * 256 + threadIdx.x;   // B*256*32*16 = 1,048,576
    int c4 = tid & 15;
    int kk = (tid >> 4) & 31;
    int y  = (tid >> 9) & 255;
    int b  = tid >> 17;

    int k0 = kk * 2;

    float sr  = d2s((float)y);
    float r0f = floorf(sr);
    int   r0  = (int)r0f;
    float fr  = sr - r0f;
    bool rv0 = (r0 >= 0);
    bool rv1 = (r0 < HP - 1);
    float wr0 = 1.0f - fr;

    const uint2* pbase = g_pooled + ((size_t)b * HP * WP) * CV4 + c4;
    const uint2* rowA  = pbase + (size_t)(rv0 ? r0     : 0) * WP * CV4;
    const uint2* rowB  = pbase + (size_t)(rv1 ? r0 + 1 : 0) * WP * CV4;

    const float4 z = make_float4(0.f, 0.f, 0.f, 0.f);

    pdl_wait();      // pooled writes visible from here

    float4 T[4];
    #pragma unroll
    for (int i = 0; i < 4; ++i) {
        int col = k0 - 1 + i;
        bool cv = (unsigned)col < (unsigned)WP;
        float4 a  = (rv0 && cv) ? unpack_h4(__ldg(rowA + (size_t)col * CV4)) : z;
        float4 bb = (rv1 && cv) ? unpack_h4(__ldg(rowB + (size_t)col * CV4)) : z;
        T[i] = blend2(a, wr0, bb, fr);
    }

    float4* op = out4 + (((size_t)b * HIN + y) * WIN + k0 * 4) * CV4 + c4;

    if (kk >= 1 && kk <= 30) {
        op[0 * CV4] = blend2(T[0], 0.375f, T[1], 0.625f);
        op[1 * CV4] = blend2(T[0], 0.125f, T[1], 0.875f);
        op[2 * CV4] = blend2(T[1], 0.875f, T[2], 0.125f);
        op[3 * CV4] = blend2(T[1], 0.625f, T[2], 0.375f);
        op[4 * CV4] = blend2(T[1], 0.375f, T[2], 0.625f);
        op[5 * CV4] = blend2(T[1], 0.125f, T[2], 0.875f);
        op[6 * CV4] = blend2(T[2], 0.875f, T[3], 0.125f);
        op[7 * CV4] = blend2(T[2], 0.625f, T[3], 0.375f);
    } else {
        int x0 = k0 * 4;
        #pragma unroll
        for (int m = 0; m < 8; ++m) {
            float sc  = d2s((float)(x0 + m));
            float c0f = floorf(sc);
            float fc  = sc - c0f;
            int idx = (int)c0f - (k0 - 1);   // 0..2
            float4 lo = (idx == 0) ? T[0] : ((idx == 1) ? T[1] : T[2]);
            float4 hi = (idx == 0) ? T[1] : ((idx == 1) ? T[2] : T[3]);
            op[m * CV4] = blend2(lo, 1.0f - fc, hi, fc);
        }
    }
}

extern "C" void kernel_launch(void* const* d_in, const int* in_sizes, int n_in,
                              void* d_out, int out_size) {
    const float4* in4 = (const float4*)d_in[0];
    float4* out4 = (float4*)d_out;

    // K1: normal launch
    colpool_kernel<<<(B * HP * WIN * CV4) / 256, 256>>>(in4);

    // K2, K3: programmatic dependent launches (overlap into producer's tail)
    cudaLaunchAttribute attrs[1];
    attrs[0].id = cudaLaunchAttributeProgrammaticStreamSerialization;
    attrs[0].val.programmaticStreamSerializationAllowed = 1;

    {
        cudaLaunchConfig_t cfg = {};
        cfg.gridDim  = dim3((B * HP * WP * CV4) / 256);
        cfg.blockDim = dim3(256);
        cfg.attrs = attrs;
        cfg.numAttrs = 1;
        cudaLaunchKernelEx(&cfg, rowpool_kernel);
    }
    {
        cudaLaunchConfig_t cfg = {};
        cfg.gridDim  = dim3((B * HIN * 32 * CV4) / 256);
        cfg.blockDim = dim3(256);
        cfg.attrs = attrs;
        cfg.numAttrs = 1;
        cudaLaunchKernelEx(&cfg, up_kernel, out4);
    }
}

// round 16
// speedup vs baseline: 1.0396x; 1.0396x over previous
#include <cuda_runtime.h>
#include <cuda_fp16.h>
#include <cuda_bf16.h>

// Problem constants
#define B    8
#define HIN  256
#define WIN  256
#define CV4  16      // C/4 channel chunks per pixel (C=64)
#define HP   64
#define WP   64

// 4 MB pooled averages in fp16 — static device scratch
__device__ uint2 g_pooled[B * HP * WP * CV4];

__device__ __forceinline__ void acc4(float4& a, const float4 v) {
    a.x += v.x; a.y += v.y; a.z += v.z; a.w += v.w;
}
__device__ __forceinline__ float4 blend2(float4 p, float wp, float4 q, float wq) {
    float4 r;
    r.x = p.x * wp + q.x * wq;
    r.y = p.y * wp + q.y * wq;
    r.z = p.z * wp + q.z * wq;
    r.w = p.w * wp + q.w * wq;
    return r;
}
__device__ __forceinline__ uint2 pack_h4(float4 v) {
    __half2 lo = __floats2half2_rn(v.x, v.y);
    __half2 hi = __floats2half2_rn(v.z, v.w);
    uint2 u;
    u.x = *reinterpret_cast<unsigned int*>(&lo);
    u.y = *reinterpret_cast<unsigned int*>(&hi);
    return u;
}
__device__ __forceinline__ float4 unpack_h4(uint2 u) {
    __half2 lo = *reinterpret_cast<__half2*>(&u.x);
    __half2 hi = *reinterpret_cast<__half2*>(&u.y);
    float2 a = __half22float2(lo);
    float2 b = __half22float2(hi);
    return make_float4(a.x, a.y, b.x, b.y);
}

// PDL primitives (validated under graph capture in R15)
__device__ __forceinline__ void pdl_wait() {
    asm volatile("griddepcontrol.wait;" ::: "memory");
}
__device__ __forceinline__ void pdl_trigger() {
    asm volatile("griddepcontrol.launch_dependents;" ::: "memory");
}

// ---------------------------------------------------------------------------
// K1: fused SAME avg-pool 6x6 stride 4, oy-pair per CTA (R9-proven, 29us).
// smem column sums fp32; final average rounded once to fp16.
// ---------------------------------------------------------------------------
__global__ __launch_bounds__(288, 5) void pool_kernel(const float4* __restrict__ in4) {
    __shared__ float4 cs[2 * 288];    // [half][xl*16+c4]

    int bid = blockIdx.x;             // b*512 + p*16 + q
    int q = bid & 15;
    int p = (bid >> 4) & 31;
    int b = bid >> 9;

    int t  = threadIdx.x;             // 0..287
    int c4 = t & 15;
    int xl = t >> 4;                  // 0..17
    int x  = 16 * q - 1 + xl;
    int rbase = 8 * p - 1;

    float4 s0 = make_float4(0.f, 0.f, 0.f, 0.f);
    float4 s1 = make_float4(0.f, 0.f, 0.f, 0.f);

    if ((unsigned)x < 256u) {
        const float4* pr = in4 + (((size_t)b * HIN + rbase) * WIN + x) * CV4 + c4;
        const size_t RS = (size_t)WIN * CV4;
        if (p != 0 && p != 31) {
            float4 v0 = __ldg(pr + 0 * RS);
            float4 v1 = __ldg(pr + 1 * RS);
            float4 v2 = __ldg(pr + 2 * RS);
            float4 v3 = __ldg(pr + 3 * RS);
            acc4(s0, v0); acc4(s0, v1); acc4(s0, v2); acc4(s0, v3);
            float4 v4 = __ldg(pr + 4 * RS);
            float4 v5 = __ldg(pr + 5 * RS);
            acc4(s0, v4); acc4(s0, v5);
            acc4(s1, v4); acc4(s1, v5);
            float4 v6 = __ldg(pr + 6 * RS);
            float4 v7 = __ldg(pr + 7 * RS);
            float4 v8 = __ldg(pr + 8 * RS);
            float4 v9 = __ldg(pr + 9 * RS);
            acc4(s1, v6); acc4(s1, v7); acc4(s1, v8); acc4(s1, v9);
        } else {
            #pragma unroll
            for (int j = 0; j < 10; ++j) {
                int r = rbase + j;
                if ((unsigned)r < 256u) {
                    float4 v = __ldg(pr + (size_t)j * RS);
                    if (j <= 5) acc4(s0, v);
                    if (j >= 4) acc4(s1, v);
                }
            }
        }
    }
    cs[t]       = s0;
    cs[288 + t] = s1;
    __syncthreads();

    if (t < 128) {
        int cc4  = t & 15;
        int oxl  = (t >> 4) & 3;
        int half = t >> 6;            // 0 or 1
        int ox   = 4 * q + oxl;
        int oy   = 2 * p + half;

        const float4* base = cs + half * 288;
        float4 acc = make_float4(0.f, 0.f, 0.f, 0.f);
        if (ox != 0) acc4(acc, base[(4 * oxl + 0) * CV4 + cc4]);
        acc4(acc, base[(4 * oxl + 1) * CV4 + cc4]);
        acc4(acc, base[(4 * oxl + 2) * CV4 + cc4]);
        acc4(acc, base[(4 * oxl + 3) * CV4 + cc4]);
        acc4(acc, base[(4 * oxl + 4) * CV4 + cc4]);
        if (ox != 63) acc4(acc, base[(4 * oxl + 5) * CV4 + cc4]);

        int nr = 6 - (oy == 0) - (oy == 63);
        int nc = 6 - (ox == 0) - (ox == 63);
        float inv = 1.0f / (float)(nr * nc);
        float4 avg = make_float4(acc.x * inv, acc.y * inv, acc.z * inv, acc.w * inv);
        g_pooled[(((size_t)b * HP + oy) * WP + ox) * CV4 + cc4] = pack_h4(avg);
    }
    pdl_trigger();   // stores done -> dependent grid may launch
}

// ---------------------------------------------------------------------------
// K2: unaverage pool, direct streaming (R9-proven 22.6us), fp16 taps,
// PDL consumer — wait placed after all index/weight math.
// ---------------------------------------------------------------------------
__device__ __forceinline__ float d2s(float d) {
    if (d < 5.5f)   return (d - 2.0f) * (1.0f / 3.5f);
    if (d > 249.5f) return (d - 249.5f) * (1.0f / 3.5f) + 62.0f;
    return (d - 1.5f) * 0.25f;
}

__global__ __launch_bounds__(256, 6) void up_kernel(float4* __restrict__ out4) {
    int tid = blockIdx.x * 256 + threadIdx.x;   // B*256*32*16 = 1,048,576
    int c4 = tid & 15;
    int kk = (tid >> 4) & 31;
    int y  = (tid >> 9) & 255;
    int b  = tid >> 17;

    int k0 = kk * 2;

    float sr  = d2s((float)y);
    float r0f = floorf(sr);
    int   r0  = (int)r0f;
    float fr  = sr - r0f;
    bool rv0 = (r0 >= 0);
    bool rv1 = (r0 < HP - 1);
    float wr0 = 1.0f - fr;

    const uint2* pbase = g_pooled + ((size_t)b * HP * WP) * CV4 + c4;
    const uint2* rowA  = pbase + (size_t)(rv0 ? r0     : 0) * WP * CV4;
    const uint2* rowB  = pbase + (size_t)(rv1 ? r0 + 1 : 0) * WP * CV4;

    const float4 z = make_float4(0.f, 0.f, 0.f, 0.f);

    pdl_wait();      // pooled writes visible past this point

    float4 T[4];
    #pragma unroll
    for (int i = 0; i < 4; ++i) {
        int col = k0 - 1 + i;
        bool cv = (unsigned)col < (unsigned)WP;
        float4 a  = (rv0 && cv) ? unpack_h4(__ldg(rowA + (size_t)col * CV4)) : z;
        float4 bb = (rv1 && cv) ? unpack_h4(__ldg(rowB + (size_t)col * CV4)) : z;
        T[i] = blend2(a, wr0, bb, fr);
    }

    float4* op = out4 + (((size_t)b * HIN + y) * WIN + k0 * 4) * CV4 + c4;

    if (kk >= 1 && kk <= 30) {
        op[0 * CV4] = blend2(T[0], 0.375f, T[1], 0.625f);
        op[1 * CV4] = blend2(T[0], 0.125f, T[1], 0.875f);
        op[2 * CV4] = blend2(T[1], 0.875f, T[2], 0.125f);
        op[3 * CV4] = blend2(T[1], 0.625f, T[2], 0.375f);
        op[4 * CV4] = blend2(T[1], 0.375f, T[2], 0.625f);
        op[5 * CV4] = blend2(T[1], 0.125f, T[2], 0.875f);
        op[6 * CV4] = blend2(T[2], 0.875f, T[3], 0.125f);
        op[7 * CV4] = blend2(T[2], 0.625f, T[3], 0.375f);
    } else {
        int x0 = k0 * 4;
        #pragma unroll
        for (int m = 0; m < 8; ++m) {
            float sc  = d2s((float)(x0 + m));
            float c0f = floorf(sc);
            float fc  = sc - c0f;
            int idx = (int)c0f - (k0 - 1);   // 0..2
            float4 lo = (idx == 0) ? T[0] : ((idx == 1) ? T[1] : T[2]);
            float4 hi = (idx == 0) ? T[1] : ((idx == 1) ? T[2] : T[3]);
            op[m * CV4] = blend2(lo, 1.0f - fc, hi, fc);
        }
    }
}

extern "C" void kernel_launch(void* const* d_in, const int* in_sizes, int n_in,
                              void* d_out, int out_size) {
    const float4* in4 = (const float4*)d_in[0];
    float4* out4 = (float4*)d_out;

    // K1: normal launch
    pool_kernel<<<B * 32 * 16, 288>>>(in4);   // 4096 CTAs

    // K2: programmatic dependent launch — overlaps into K1's tail
    cudaLaunchAttribute attrs[1];
    attrs[0].id = cudaLaunchAttributeProgrammaticStreamSerialization;
    attrs[0].val.programmaticStreamSerializationAllowed = 1;

    cudaLaunchConfig_t cfg = {};
    cfg.gridDim  = dim3((B * HIN * 32 * CV4) / 256);   // 4096 CTAs
    cfg.blockDim = dim3(256);
    cfg.attrs = attrs;
    cfg.numAttrs = 1;
    cudaLaunchKernelEx(&cfg, up_kernel, out4);
}